// round 16
// baseline (speedup 1.0000x reference)
#include <cuda_runtime.h>
#include <cuda_fp16.h>
#include <cstdint>
#include <math.h>

#define S_IMG 4096
#define S_TXT 512
#define S_TOT 4608
#define D_MODEL 3072
#define NH 24
#define NKV 8
#define HD 128

// ---------------- scratch buffers ----------------
__device__ __align__(16) __half g_hsh[S_IMG * D_MODEL];
__device__ __align__(16) __half g_hsl[S_IMG * D_MODEL];
__device__ __align__(16) __half g_ehsh[S_TXT * D_MODEL];
__device__ __align__(16) __half g_ehsl[S_TXT * D_MODEL];
__device__ __align__(16) __half g_wq[D_MODEL * 3072];
__device__ __align__(16) __half g_wk[D_MODEL * 1024];
__device__ __align__(16) __half g_wv[D_MODEL * 1024];
__device__ __align__(16) __half g_awq[D_MODEL * 3072];
__device__ __align__(16) __half g_awk[D_MODEL * 1024];
__device__ __align__(16) __half g_awv[D_MODEL * 1024];
__device__ __align__(16) __half g_wout[3072 * D_MODEL];
__device__ __align__(16) __half g_waout[3072 * D_MODEL];
__device__ __align__(16) __half g_qhb[NH * S_TOT * HD];
__device__ __align__(16) __half g_qlb[NH * S_TOT * HD];
__device__ __align__(16) __half g_kb[NKV * S_TOT * HD];
__device__ __align__(16) __half g_vb[NKV * S_TOT * HD];
__device__ __align__(16) __half g_oh[S_TOT * 3072];
__device__ __align__(16) __half g_ol[S_TOT * 3072];

// ---------------- PTX helpers ----------------
__device__ __forceinline__ uint32_t cvta_s(const void* p) {
    return (uint32_t)__cvta_generic_to_shared(p);
}
__device__ __forceinline__ void ldsm4(uint32_t* r, uint32_t addr) {
    asm volatile("ldmatrix.sync.aligned.m8n8.x4.shared.b16 {%0,%1,%2,%3},[%4];"
                 : "=r"(r[0]), "=r"(r[1]), "=r"(r[2]), "=r"(r[3]) : "r"(addr));
}
__device__ __forceinline__ void ldsm4t(uint32_t* r, uint32_t addr) {
    asm volatile("ldmatrix.sync.aligned.m8n8.x4.trans.shared.b16 {%0,%1,%2,%3},[%4];"
                 : "=r"(r[0]), "=r"(r[1]), "=r"(r[2]), "=r"(r[3]) : "r"(addr));
}
__device__ __forceinline__ void mma16816(float* c, const uint32_t* a, uint32_t b0, uint32_t b1) {
    asm volatile(
        "mma.sync.aligned.m16n8k16.row.col.f32.f16.f16.f32 "
        "{%0,%1,%2,%3},{%4,%5,%6,%7},{%8,%9},{%0,%1,%2,%3};"
        : "+f"(c[0]), "+f"(c[1]), "+f"(c[2]), "+f"(c[3])
        : "r"(a[0]), "r"(a[1]), "r"(a[2]), "r"(a[3]), "r"(b0), "r"(b1));
}
__device__ __forceinline__ uint32_t packh2(float x, float y) {
    __half2 h = __floats2half2_rn(x, y);
    return *(uint32_t*)&h;
}
__device__ __forceinline__ void cp16(uint32_t s, const void* g) {
    asm volatile("cp.async.cg.shared.global [%0], [%1], 16;" :: "r"(s), "l"(g));
}
__device__ __forceinline__ void cp_commit() {
    asm volatile("cp.async.commit_group;" ::: "memory");
}

// ---------------- fp32 -> split fp16 (grid-stride) ----------------
__global__ void split_k(const float* __restrict__ in, __half* __restrict__ hi,
                        __half* __restrict__ lo, int n4) {
    int stride = gridDim.x * blockDim.x;
    for (int q = blockIdx.x * blockDim.x + threadIdx.x; q < n4; q += stride) {
        int i = q * 4;
        float4 v = *(const float4*)(in + i);
        __half h0 = __float2half_rn(v.x), h1 = __float2half_rn(v.y);
        __half h2 = __float2half_rn(v.z), h3 = __float2half_rn(v.w);
        *(__half2*)(hi + i) = __halves2half2(h0, h1);
        *(__half2*)(hi + i + 2) = __halves2half2(h2, h3);
        *(__half2*)(lo + i) = __floats2half2_rn(v.x - __half2float(h0), v.y - __half2float(h1));
        *(__half2*)(lo + i + 2) = __floats2half2_rn(v.z - __half2float(h2), v.w - __half2float(h3));
    }
}

// ---------------- fused fp32 -> fp16 for all 8 weight tensors ----------------
struct F2HJobs {
    const float* src[8];
    __half* dst[8];
    int cum[9];
};
__global__ void f2h_multi(F2HJobs j, int total4) {
    int stride = gridDim.x * blockDim.x;
    for (int q = blockIdx.x * blockDim.x + threadIdx.x; q < total4; q += stride) {
        int s = 0;
#pragma unroll
        for (int t = 0; t < 7; t++) s += (q >= j.cum[t + 1]) ? 1 : 0;
        int i = (q - j.cum[s]) * 4;
        float4 v = *(const float4*)(j.src[s] + i);
        *(__half2*)(j.dst[s] + i) = __floats2half2_rn(v.x, v.y);
        *(__half2*)(j.dst[s] + i + 2) = __floats2half2_rn(v.z, v.w);
    }
}

// ---------------- shared 2-term GEMM mainloop, BK=64, 2-stage, 2 CTAs/SM ----------------
// Stage layout (halves): Ah[0,8192) Al[8192,16384) Bh[16384,24576)
#define GS_STAGE 24576
#define GS_BYTES (2 * GS_STAGE * 2)

__device__ __forceinline__ void gemm_mainloop(
    const __half* __restrict__ Ah, const __half* __restrict__ Al, int arow0,
    const __half* __restrict__ Bh, int N, int n0,
    __half* smp, float c[2][8][4], int tid)
{
    const int lane = tid & 31, warp = tid >> 5;
    const int m_off = (warp >> 1) * 32, n_off = (warp & 1) * 64;

    auto issue = [&](int stage, int k0) {
        __half* st = smp + stage * GS_STAGE;
#pragma unroll
        for (int i = 0; i < 4; i++) {
            int u = tid + i * 256;
            int aR = u >> 3, aC = u & 7;
            uint32_t d = cvta_s(st + aR * 64 + ((aC ^ (aR & 3)) << 3));
            size_t go = (size_t)(arow0 + aR) * D_MODEL + k0 + aC * 8;
            cp16(d, Ah + go);
            cp16(d + 16384, Al + go);
            int bR = u >> 4, bC = u & 15;
            cp16(cvta_s(st + 16384 + bR * 128 + ((bC ^ (bR & 7)) << 3)),
                 Bh + (size_t)(k0 + bR) * N + n0 + bC * 8);
        }
    };

    const int nkt = D_MODEL >> 6;   // 48
    issue(0, 0); cp_commit();

    for (int kt = 0; kt < nkt; kt++) {
        asm volatile("cp.async.wait_group 0;" ::: "memory");
        __syncthreads();
        if (kt + 1 < nkt) issue((kt + 1) & 1, (kt + 1) * 64);
        cp_commit();

        __half* st = smp + (kt & 1) * GS_STAGE;
        __half* Ash = st;
        __half* Asl = st + 8192;
        __half* Bsh = st + 16384;
#pragma unroll
        for (int kk = 0; kk < 4; kk++) {
            uint32_t ah[2][4], al[2][4];
#pragma unroll
            for (int mi = 0; mi < 2; mi++) {
                int row = m_off + mi * 16 + (lane & 15);
                int c8 = kk * 2 + (lane >> 4);
                int off = row * 64 + ((c8 ^ (row & 3)) << 3);
                ldsm4(ah[mi], cvta_s(Ash + off));
                ldsm4(al[mi], cvta_s(Asl + off));
            }
#pragma unroll
            for (int njp = 0; njp < 4; njp++) {
                int row = kk * 16 + (lane & 15);
                int c8 = (n_off >> 3) + njp * 2 + (lane >> 4);
                int off = row * 128 + ((c8 ^ (row & 7)) << 3);
                uint32_t bh[4];
                ldsm4t(bh, cvta_s(Bsh + off));
#pragma unroll
                for (int mi = 0; mi < 2; mi++) {
                    mma16816(c[mi][2 * njp], ah[mi], bh[0], bh[1]);
                    mma16816(c[mi][2 * njp], al[mi], bh[0], bh[1]);
                    mma16816(c[mi][2 * njp + 1], ah[mi], bh[2], bh[3]);
                    mma16816(c[mi][2 * njp + 1], al[mi], bh[2], bh[3]);
                }
            }
        }
        __syncthreads();
    }
}

// ---------------- fused QKV projection + RMSNorm + RoPE (one launch) ----------------
// grid (40, 36): y<4 -> text rows, else image rows; x<24 -> Q, x<32 -> K, else V.
__global__ __launch_bounds__(256, 2) void qkv_k(
    const float* __restrict__ bq, const float* __restrict__ bk, const float* __restrict__ bv,
    const float* __restrict__ abq, const float* __restrict__ abk, const float* __restrict__ abv,
    const float* __restrict__ nq, const float* __restrict__ nk,
    const float* __restrict__ anq, const float* __restrict__ ank,
    const float* __restrict__ rope, float qscale)
{
    extern __shared__ __align__(16) __half smp[];
    const int tid = threadIdx.x;
    const int lane = tid & 31, warp = tid >> 5;
    const int m_off = (warp >> 1) * 32, n_off = (warp & 1) * 64;
    const int by = blockIdx.y, bx = blockIdx.x;
    const bool txt = by < 4;
    const __half* Ah = txt ? g_ehsh : g_hsh;
    const __half* Al = txt ? g_ehsl : g_hsl;
    const int arow0 = txt ? by * 128 : (by - 4) * 128;
    const int jrow0 = by * 128;
    const int n0g = bx * 128;

    int seg, lc0, Nw;
    const __half* W;
    const float* bias;
    if (n0g < 3072)      { seg = 0; lc0 = n0g;        Nw = 3072; W = txt ? g_awq : g_wq; bias = txt ? abq : bq; }
    else if (n0g < 4096) { seg = 1; lc0 = n0g - 3072; Nw = 1024; W = txt ? g_awk : g_wk; bias = txt ? abk : bk; }
    else                 { seg = 2; lc0 = n0g - 4096; Nw = 1024; W = txt ? g_awv : g_wv; bias = txt ? abv : bv; }

    float c[2][8][4];
#pragma unroll
    for (int mi = 0; mi < 2; mi++)
#pragma unroll
        for (int nj = 0; nj < 8; nj++)
#pragma unroll
            for (int t = 0; t < 4; t++) c[mi][nj][t] = 0.f;

    gemm_mainloop(Ah, Al, arow0, W, Nw, lc0, smp, c, tid);

    const int head = lc0 >> 7;

    if (seg == 2) {
#pragma unroll
        for (int mi = 0; mi < 2; mi++) {
#pragma unroll
            for (int nj = 0; nj < 8; nj++) {
                int r0 = m_off + mi * 16 + (lane >> 2);
                int r1 = r0 + 8;
                int col = n_off + nj * 8 + ((lane & 3) << 1);
                float bx_ = bias[lc0 + col], by_ = bias[lc0 + col + 1];
                *(__half2*)(g_vb + ((size_t)head * S_TOT + jrow0 + r0) * HD + col) =
                    __floats2half2_rn(c[mi][nj][0] + bx_, c[mi][nj][1] + by_);
                *(__half2*)(g_vb + ((size_t)head * S_TOT + jrow0 + r1) * HD + col) =
                    __floats2half2_rn(c[mi][nj][2] + bx_, c[mi][nj][3] + by_);
            }
        }
        return;
    }

    // Q/K: add bias in place, then fused RMSNorm + RoPE with register/shuffle reduction.
#pragma unroll
    for (int mi = 0; mi < 2; mi++) {
#pragma unroll
        for (int nj = 0; nj < 8; nj++) {
            int col = n_off + nj * 8 + ((lane & 3) << 1);
            float bx_ = bias[lc0 + col], by_ = bias[lc0 + col + 1];
            c[mi][nj][0] += bx_; c[mi][nj][1] += by_;
            c[mi][nj][2] += bx_; c[mi][nj][3] += by_;
        }
    }
    float part[2][2];
#pragma unroll
    for (int mi = 0; mi < 2; mi++) {
        float s0 = 0.f, s1 = 0.f;
#pragma unroll
        for (int nj = 0; nj < 8; nj++) {
            s0 += c[mi][nj][0] * c[mi][nj][0] + c[mi][nj][1] * c[mi][nj][1];
            s1 += c[mi][nj][2] * c[mi][nj][2] + c[mi][nj][3] * c[mi][nj][3];
        }
        s0 += __shfl_xor_sync(0xffffffffu, s0, 1);
        s0 += __shfl_xor_sync(0xffffffffu, s0, 2);
        s1 += __shfl_xor_sync(0xffffffffu, s1, 1);
        s1 += __shfl_xor_sync(0xffffffffu, s1, 2);
        part[mi][0] = s0; part[mi][1] = s1;
    }
    float* red = (float*)smp;
    if ((lane & 3) == 0) {
#pragma unroll
        for (int mi = 0; mi < 2; mi++) {
            red[((warp * 2 + mi) * 2 + 0) * 8 + (lane >> 2)] = part[mi][0];
            red[((warp * 2 + mi) * 2 + 1) * 8 + (lane >> 2)] = part[mi][1];
        }
    }
    __syncthreads();

    const float* wnorm = (seg == 0) ? (txt ? anq : nq) : (txt ? ank : nk);
    const float oscale = (seg == 0) ? qscale : 1.0f;
    __half* outh = (seg == 0) ? g_qhb : g_kb;
    __half* outl = (seg == 0) ? g_qlb : (__half*)0;

#pragma unroll
    for (int mi = 0; mi < 2; mi++) {
#pragma unroll
        for (int rh = 0; rh < 2; rh++) {
            float sum = part[mi][rh] +
                red[(((warp ^ 1) * 2 + mi) * 2 + rh) * 8 + (lane >> 2)];
            float rr = rsqrtf(sum * (1.0f / HD) + 1e-6f);
            int r = m_off + mi * 16 + rh * 8 + (lane >> 2);
            int s = jrow0 + r;
            size_t rbase = ((size_t)head * S_TOT + s) * HD;
            const float* cosp = rope + (size_t)s * HD;
            const float* sinp = rope + (size_t)S_TOT * HD + (size_t)s * HD;
#pragma unroll
            for (int nj = 0; nj < 8; nj++) {
                int col = n_off + nj * 8 + ((lane & 3) << 1);
                float v0 = c[mi][nj][rh * 2 + 0];
                float v1 = c[mi][nj][rh * 2 + 1];
                float2 wn = *(const float2*)(wnorm + col);
                float y0 = v0 * rr * wn.x;
                float y1 = v1 * rr * wn.y;
                float2 cc = *(const float2*)(cosp + col);
                float2 sn = *(const float2*)(sinp + col);
                float o0 = (y0 * cc.x - y1 * sn.x) * oscale;
                float o1 = (y1 * cc.y + y0 * sn.y) * oscale;
                __half h0 = __float2half_rn(o0), h1 = __float2half_rn(o1);
                *(__half2*)(outh + rbase + col) = __halves2half2(h0, h1);
                if (outl) {
                    *(__half2*)(outl + rbase + col) =
                        __floats2half2_rn(o0 - __half2float(h0), o1 - __half2float(h1));
                }
            }
        }
    }
}

// ---------------- fused output projections (one launch) ----------------
__global__ __launch_bounds__(256, 2) void oproj_k(
    const float* __restrict__ bout, const float* __restrict__ baout, float* __restrict__ out)
{
    extern __shared__ __align__(16) __half smp[];
    const int tid = threadIdx.x;
    const int lane = tid & 31, warp = tid >> 5;
    const int m_off = (warp >> 1) * 32, n_off = (warp & 1) * 64;
    const int by = blockIdx.y, bx = blockIdx.x;
    const bool txt = by < 4;
    const int arow0 = by * 128;
    const int crow0 = txt ? 4096 + by * 128 : by * 128 - 512;
    const __half* W = txt ? g_waout : g_wout;
    const float* bias = txt ? baout : bout;
    const int n0 = bx * 128;

    float c[2][8][4];
#pragma unroll
    for (int mi = 0; mi < 2; mi++)
#pragma unroll
        for (int nj = 0; nj < 8; nj++)
#pragma unroll
            for (int t = 0; t < 4; t++) c[mi][nj][t] = 0.f;

    gemm_mainloop(g_oh, g_ol, arow0, W, 3072, n0, smp, c, tid);

#pragma unroll
    for (int mi = 0; mi < 2; mi++) {
#pragma unroll
        for (int nj = 0; nj < 8; nj++) {
            int r0 = m_off + mi * 16 + (lane >> 2);
            int r1 = r0 + 8;
            int col = n0 + n_off + nj * 8 + ((lane & 3) << 1);
            float bx_ = bias[col], by_ = bias[col + 1];
            *(float2*)(out + (size_t)(crow0 + r0) * 3072 + col) =
                make_float2(c[mi][nj][0] + bx_, c[mi][nj][1] + by_);
            *(float2*)(out + (size_t)(crow0 + r1) * 3072 + col) =
                make_float2(c[mi][nj][2] + bx_, c[mi][nj][3] + by_);
        }
    }
}

// ---------------- flash attention: ping-pong QK/softmax/PV overlap, 3-buffer KV ring ----------------
#define AT_STEPS (S_TOT / 64)
#define AT_SMEM ((16384 + 16384 + 3 * 8192 + 3 * 8192) * 2)

__global__ __launch_bounds__(256) void attn_k(
    const __half* __restrict__ qh, const __half* __restrict__ qlg,
    const __half* __restrict__ kg, const __half* __restrict__ vg,
    __half* __restrict__ oh, __half* __restrict__ ol)
{
    extern __shared__ __align__(16) __half sm[];
    __half* Qh = sm;                    // 128x128
    __half* Ql = sm + 16384;            // 128x128
    __half* Kb = sm + 32768;            // 3 x 64x128
    __half* Vb = sm + 57344;            // 3 x 64x128
    const int tid = threadIdx.x, lane = tid & 31, w = tid >> 5;
    const int h = blockIdx.y, m0 = blockIdx.x * 128;
    const int kvh = h / 3;

    // Q tiles -> smem (own cp.async group)
    const __half* qbh = qh + ((size_t)h * S_TOT + m0) * HD;
    const __half* qbl = qlg + ((size_t)h * S_TOT + m0) * HD;
#pragma unroll
    for (int t = 0; t < 8; t++) {
        int cid = tid + t * 256;
        int r = cid >> 4, c8 = cid & 15;
        int off = r * 128 + ((c8 ^ (r & 7)) << 3);
        cp16(cvta_s(Qh + off), qbh + (size_t)r * HD + c8 * 8);
        cp16(cvta_s(Ql + off), qbl + (size_t)r * HD + c8 * 8);
    }
    cp_commit();

    const __half* kb0 = kg + (size_t)kvh * S_TOT * HD;
    const __half* vb0 = vg + (size_t)kvh * S_TOT * HD;
    auto issue_kv = [&](int n, int buf) {
        const __half* kb = kb0 + (size_t)n * 64 * HD;
        const __half* vb = vb0 + (size_t)n * 64 * HD;
        __half* Kd = Kb + buf * 8192;
        __half* Vd = Vb + buf * 8192;
#pragma unroll
        for (int t = 0; t < 4; t++) {
            int cid = tid + t * 256;
            int r = cid >> 4, c8 = cid & 15;
            int off = r * 128 + ((c8 ^ (r & 7)) << 3);
            cp16(cvta_s(Kd + off), kb + (size_t)r * HD + c8 * 8);
            cp16(cvta_s(Vd + off), vb + (size_t)r * HD + c8 * 8);
        }
    };
    issue_kv(0, 0); cp_commit();
    issue_kv(1, 1); cp_commit();

    // Q ready (2 younger KV groups pending), preload Q fragments into registers
    asm volatile("cp.async.wait_group 2;" ::: "memory");
    __syncthreads();
    uint32_t qa[8][4], qla[8][4];
#pragma unroll
    for (int dk = 0; dk < 8; dk++) {
        int row = w * 16 + (lane & 15);
        int c8 = dk * 2 + (lane >> 4);
        int off = row * 128 + ((c8 ^ (row & 7)) << 3);
        ldsm4(qa[dk], cvta_s(Qh + off));
        ldsm4(qla[dk], cvta_s(Ql + off));
    }

    float oa[16][4];
#pragma unroll
    for (int nj = 0; nj < 16; nj++)
#pragma unroll
        for (int t = 0; t < 4; t++) oa[nj][t] = 0.f;
    float mI0 = -INFINITY, mI1 = -INFINITY, lI0 = 0.f, lI1 = 0.f;

    float s[8][4];
    // KV0 ready -> QK(0)
    asm volatile("cp.async.wait_group 1;" ::: "memory");
    __syncthreads();
#pragma unroll
    for (int j = 0; j < 8; j++)
#pragma unroll
        for (int t = 0; t < 4; t++) s[j][t] = 0.f;
#pragma unroll
    for (int dk = 0; dk < 8; dk++) {
#pragma unroll
        for (int njp = 0; njp < 4; njp++) {
            int row = njp * 16 + (lane & 7) + ((lane >> 4) << 3);
            int c8 = dk * 2 + ((lane >> 3) & 1);
            uint32_t b[4];
            ldsm4(b, cvta_s(Kb + row * 128 + ((c8 ^ (row & 7)) << 3)));
            mma16816(s[2 * njp], qa[dk], b[0], b[1]);
            mma16816(s[2 * njp], qla[dk], b[0], b[1]);
            mma16816(s[2 * njp + 1], qa[dk], b[2], b[3]);
            mma16816(s[2 * njp + 1], qla[dk], b[2], b[3]);
        }
    }

    for (int it = 0; it < AT_STEPS; it++) {
        // ---- softmax on s (scores of step it) ----
        float mx0 = -INFINITY, mx1 = -INFINITY;
#pragma unroll
        for (int j = 0; j < 8; j++) {
            mx0 = fmaxf(mx0, fmaxf(s[j][0], s[j][1]));
            mx1 = fmaxf(mx1, fmaxf(s[j][2], s[j][3]));
        }
        mx0 = fmaxf(mx0, __shfl_xor_sync(0xffffffffu, mx0, 1));
        mx0 = fmaxf(mx0, __shfl_xor_sync(0xffffffffu, mx0, 2));
        mx1 = fmaxf(mx1, __shfl_xor_sync(0xffffffffu, mx1, 1));
        mx1 = fmaxf(mx1, __shfl_xor_sync(0xffffffffu, mx1, 2));
        float mn0 = fmaxf(mI0, mx0), mn1 = fmaxf(mI1, mx1);
        float al0 = exp2f(mI0 - mn0), al1 = exp2f(mI1 - mn1);
        mI0 = mn0; mI1 = mn1;
        float rs0 = 0.f, rs1 = 0.f;
#pragma unroll
        for (int j = 0; j < 8; j++) {
            s[j][0] = exp2f(s[j][0] - mn0);
            s[j][1] = exp2f(s[j][1] - mn0);
            s[j][2] = exp2f(s[j][2] - mn1);
            s[j][3] = exp2f(s[j][3] - mn1);
            rs0 += s[j][0] + s[j][1];
            rs1 += s[j][2] + s[j][3];
        }
        rs0 += __shfl_xor_sync(0xffffffffu, rs0, 1);
        rs0 += __shfl_xor_sync(0xffffffffu, rs0, 2);
        rs1 += __shfl_xor_sync(0xffffffffu, rs1, 1);
        rs1 += __shfl_xor_sync(0xffffffffu, rs1, 2);
        lI0 = lI0 * al0 + rs0;
        lI1 = lI1 * al1 + rs1;
#pragma unroll
        for (int nj = 0; nj < 16; nj++) {
            oa[nj][0] *= al0; oa[nj][1] *= al0;
            oa[nj][2] *= al1; oa[nj][3] *= al1;
        }
        uint32_t pa[4][4];
#pragma unroll
        for (int kc = 0; kc < 4; kc++) {
            pa[kc][0] = packh2(s[2 * kc][0], s[2 * kc][1]);
            pa[kc][1] = packh2(s[2 * kc][2], s[2 * kc][3]);
            pa[kc][2] = packh2(s[2 * kc + 1][0], s[2 * kc + 1][1]);
            pa[kc][3] = packh2(s[2 * kc + 1][2], s[2 * kc + 1][3]);
        }

        // ---- QK(it+1) issued before PV(it): softmax(it+1) hides behind PV(it) ----
        if (it + 1 < AT_STEPS) {
            asm volatile("cp.async.wait_group 0;" ::: "memory");
            __syncthreads();                 // KV(it+1) ready; all warps past PV(it-1)
            if (it + 2 < AT_STEPS) { issue_kv(it + 2, (it + 2) % 3); cp_commit(); }
            __half* Ksn = Kb + ((it + 1) % 3) * 8192;
#pragma unroll
            for (int j = 0; j < 8; j++)
#pragma unroll
                for (int t = 0; t < 4; t++) s[j][t] = 0.f;
#pragma unroll
            for (int dk = 0; dk < 8; dk++) {
#pragma unroll
                for (int njp = 0; njp < 4; njp++) {
                    int row = njp * 16 + (lane & 7) + ((lane >> 4) << 3);
                    int c8 = dk * 2 + ((lane >> 3) & 1);
                    uint32_t b[4];
                    ldsm4(b, cvta_s(Ksn + row * 128 + ((c8 ^ (row & 7)) << 3)));
                    mma16816(s[2 * njp], qa[dk], b[0], b[1]);
                    mma16816(s[2 * njp], qla[dk], b[0], b[1]);
                    mma16816(s[2 * njp + 1], qa[dk], b[2], b[3]);
                    mma16816(s[2 * njp + 1], qla[dk], b[2], b[3]);
                }
            }
        }

        // ---- PV(it) ----
        __half* Vs = Vb + (it % 3) * 8192;
#pragma unroll
        for (int kc = 0; kc < 4; kc++) {
#pragma unroll
            for (int njp = 0; njp < 8; njp++) {
                int row = kc * 16 + (lane & 15);
                int c8 = njp * 2 + (lane >> 4);
                uint32_t b[4];
                ldsm4t(b, cvta_s(Vs + row * 128 + ((c8 ^ (row & 7)) << 3)));
                mma16816(oa[2 * njp], pa[kc], b[0], b[1]);
                mma16816(oa[2 * njp + 1], pa[kc], b[2], b[3]);
            }
        }
    }

    float inv0 = 1.f / lI0, inv1 = 1.f / lI1;
    int gr0 = m0 + w * 16 + (lane >> 2);
    int gr1 = gr0 + 8;
#pragma unroll
    for (int nj = 0; nj < 16; nj++) {
        int col = h * 128 + nj * 8 + ((lane & 3) << 1);
        float v00 = oa[nj][0] * inv0, v01 = oa[nj][1] * inv0;
        float v10 = oa[nj][2] * inv1, v11 = oa[nj][3] * inv1;
        __half h00 = __float2half_rn(v00), h01 = __float2half_rn(v01);
        __half h10 = __float2half_rn(v10), h11 = __float2half_rn(v11);
        *(__half2*)(oh + (size_t)gr0 * 3072 + col) = __halves2half2(h00, h01);
        *(__half2*)(oh + (size_t)gr1 * 3072 + col) = __halves2half2(h10, h11);
        *(__half2*)(ol + (size_t)gr0 * 3072 + col) =
            __floats2half2_rn(v00 - __half2float(h00), v01 - __half2float(h01));
        *(__half2*)(ol + (size_t)gr1 * 3072 + col) =
            __floats2half2_rn(v10 - __half2float(h10), v11 - __half2float(h11));
    }
}

// ---------------- launch ----------------
extern "C" void kernel_launch(void* const* d_in, const int* in_sizes, int n_in,
                              void* d_out, int out_size)
{
    const float* hs    = (const float*)d_in[0];
    const float* ehs   = (const float*)d_in[1];
    const float* rope  = (const float*)d_in[2];
    const float* Wq    = (const float*)d_in[3];
    const float* bq    = (const float*)d_in[4];
    const float* Wk    = (const float*)d_in[5];
    const float* bk    = (const float*)d_in[6];
    const float* Wv    = (const float*)d_in[7];
    const float* bv    = (const float*)d_in[8];
    const float* aWq   = (const float*)d_in[9];
    const float* abq   = (const float*)d_in[10];
    const float* aWk   = (const float*)d_in[11];
    const float* abk   = (const float*)d_in[12];
    const float* aWv   = (const float*)d_in[13];
    const float* abv   = (const float*)d_in[14];
    const float* nq    = (const float*)d_in[15];
    const float* nk    = (const float*)d_in[16];
    const float* anq   = (const float*)d_in[17];
    const float* ank   = (const float*)d_in[18];
    const float* Wout  = (const float*)d_in[19];
    const float* bout  = (const float*)d_in[20];
    const float* Waout = (const float*)d_in[21];
    const float* baout = (const float*)d_in[22];
    float* out = (float*)d_out;

    __half *hsh, *hsl, *ehsh, *ehsl;
    __half *wq, *wk, *wv, *awq, *awk, *awv, *wout, *waout;
    __half *qhb, *qlb, *k, *v, *oh, *ol;
    cudaGetSymbolAddress((void**)&hsh, g_hsh);
    cudaGetSymbolAddress((void**)&hsl, g_hsl);
    cudaGetSymbolAddress((void**)&ehsh, g_ehsh);
    cudaGetSymbolAddress((void**)&ehsl, g_ehsl);
    cudaGetSymbolAddress((void**)&wq, g_wq);
    cudaGetSymbolAddress((void**)&wk, g_wk);
    cudaGetSymbolAddress((void**)&wv, g_wv);
    cudaGetSymbolAddress((void**)&awq, g_awq);
    cudaGetSymbolAddress((void**)&awk, g_awk);
    cudaGetSymbolAddress((void**)&awv, g_awv);
    cudaGetSymbolAddress((void**)&wout, g_wout);
    cudaGetSymbolAddress((void**)&waout, g_waout);
    cudaGetSymbolAddress((void**)&qhb, g_qhb);
    cudaGetSymbolAddress((void**)&qlb, g_qlb);
    cudaGetSymbolAddress((void**)&k, g_kb);
    cudaGetSymbolAddress((void**)&v, g_vb);
    cudaGetSymbolAddress((void**)&oh, g_oh);
    cudaGetSymbolAddress((void**)&ol, g_ol);

    // activations: split hi/lo (grid-stride)
    split_k<<<1184, 256>>>(hs, hsh, hsl, (S_IMG * D_MODEL) / 4);
    split_k<<<296, 256>>>(ehs, ehsh, ehsl, (S_TXT * D_MODEL) / 4);

    // weights: one fused fp16 conversion over all 8 tensors
    {
        F2HJobs j;
        const float* srcs[8] = {Wq, Wk, Wv, aWq, aWk, aWv, Wout, Waout};
        __half* dsts[8] = {wq, wk, wv, awq, awk, awv, wout, waout};
        int sizes[8] = {D_MODEL * 3072, D_MODEL * 1024, D_MODEL * 1024,
                        D_MODEL * 3072, D_MODEL * 1024, D_MODEL * 1024,
                        3072 * D_MODEL, 3072 * D_MODEL};
        int acc = 0;
        for (int i = 0; i < 8; i++) {
            j.src[i] = srcs[i];
            j.dst[i] = dsts[i];
            j.cum[i] = acc;
            acc += sizes[i] / 4;
        }
        j.cum[8] = acc;
        f2h_multi<<<1184, 256>>>(j, acc);
    }

    cudaFuncSetAttribute(qkv_k, cudaFuncAttributeMaxDynamicSharedMemorySize, GS_BYTES);
    cudaFuncSetAttribute(oproj_k, cudaFuncAttributeMaxDynamicSharedMemorySize, GS_BYTES);

    // fused QKV projections + RMSNorm + RoPE: one launch
    const float qscale = 0.08838834764831845f * 1.4426950408889634f;
    qkv_k<<<dim3(40, 36), 256, GS_BYTES>>>(bq, bk, bv, abq, abk, abv,
                                           nq, nk, anq, ank, rope, qscale);

    // attention
    cudaFuncSetAttribute(attn_k, cudaFuncAttributeMaxDynamicSharedMemorySize, AT_SMEM);
    attn_k<<<dim3(S_TOT / 128, NH), 256, AT_SMEM>>>(qhb, qlb, k, v, oh, ol);

    // fused output projections: one launch for hid + enc
    oproj_k<<<dim3(24, 36), 256, GS_BYTES>>>(bout, baout, out);
}

// round 17
// speedup vs baseline: 1.0232x; 1.0232x over previous
#include <cuda_runtime.h>
#include <cuda_fp16.h>
#include <cstdint>
#include <math.h>

#define S_IMG 4096
#define S_TXT 512
#define S_TOT 4608
#define D_MODEL 3072
#define NH 24
#define NKV 8
#define HD 128

// ---------------- scratch buffers ----------------
__device__ __align__(16) __half g_hsh[S_IMG * D_MODEL];
__device__ __align__(16) __half g_hsl[S_IMG * D_MODEL];
__device__ __align__(16) __half g_ehsh[S_TXT * D_MODEL];
__device__ __align__(16) __half g_ehsl[S_TXT * D_MODEL];
__device__ __align__(16) __half g_wq[D_MODEL * 3072];
__device__ __align__(16) __half g_wk[D_MODEL * 1024];
__device__ __align__(16) __half g_wv[D_MODEL * 1024];
__device__ __align__(16) __half g_awq[D_MODEL * 3072];
__device__ __align__(16) __half g_awk[D_MODEL * 1024];
__device__ __align__(16) __half g_awv[D_MODEL * 1024];
__device__ __align__(16) __half g_wout[3072 * D_MODEL];
__device__ __align__(16) __half g_waout[3072 * D_MODEL];
__device__ __align__(16) __half g_qhb[NH * S_TOT * HD];
__device__ __align__(16) __half g_qlb[NH * S_TOT * HD];
__device__ __align__(16) __half g_kb[NKV * S_TOT * HD];
__device__ __align__(16) __half g_vb[NKV * S_TOT * HD];
__device__ __align__(16) __half g_oh[S_TOT * 3072];
__device__ __align__(16) __half g_ol[S_TOT * 3072];

// ---------------- PTX helpers ----------------
__device__ __forceinline__ uint32_t cvta_s(const void* p) {
    return (uint32_t)__cvta_generic_to_shared(p);
}
__device__ __forceinline__ void ldsm4(uint32_t* r, uint32_t addr) {
    asm volatile("ldmatrix.sync.aligned.m8n8.x4.shared.b16 {%0,%1,%2,%3},[%4];"
                 : "=r"(r[0]), "=r"(r[1]), "=r"(r[2]), "=r"(r[3]) : "r"(addr));
}
__device__ __forceinline__ void ldsm4t(uint32_t* r, uint32_t addr) {
    asm volatile("ldmatrix.sync.aligned.m8n8.x4.trans.shared.b16 {%0,%1,%2,%3},[%4];"
                 : "=r"(r[0]), "=r"(r[1]), "=r"(r[2]), "=r"(r[3]) : "r"(addr));
}
__device__ __forceinline__ void mma16816(float* c, const uint32_t* a, uint32_t b0, uint32_t b1) {
    asm volatile(
        "mma.sync.aligned.m16n8k16.row.col.f32.f16.f16.f32 "
        "{%0,%1,%2,%3},{%4,%5,%6,%7},{%8,%9},{%0,%1,%2,%3};"
        : "+f"(c[0]), "+f"(c[1]), "+f"(c[2]), "+f"(c[3])
        : "r"(a[0]), "r"(a[1]), "r"(a[2]), "r"(a[3]), "r"(b0), "r"(b1));
}
__device__ __forceinline__ uint32_t packh2(float x, float y) {
    __half2 h = __floats2half2_rn(x, y);
    return *(uint32_t*)&h;
}
__device__ __forceinline__ void cp16(uint32_t s, const void* g) {
    asm volatile("cp.async.cg.shared.global [%0], [%1], 16;" :: "r"(s), "l"(g));
}
__device__ __forceinline__ void cp_commit() {
    asm volatile("cp.async.commit_group;" ::: "memory");
}

// ---------------- fused fp32 -> fp16 conversions: all 10 tensors, one launch ----------------
// Jobs 0-1 (activations): write hi + lo. Jobs 2-9 (weights): hi only (lo == null).
struct CvtJobs {
    const float* src[10];
    __half* hi[10];
    __half* lo[10];
    int cum[11];    // prefix sums in quads (4 elements)
};
__global__ void cvt_all(CvtJobs j, int total4) {
    int stride = gridDim.x * blockDim.x;
    for (int q = blockIdx.x * blockDim.x + threadIdx.x; q < total4; q += stride) {
        int s = 0;
#pragma unroll
        for (int t = 0; t < 9; t++) s += (q >= j.cum[t + 1]) ? 1 : 0;
        int i = (q - j.cum[s]) * 4;
        float4 v = *(const float4*)(j.src[s] + i);
        __half h0 = __float2half_rn(v.x), h1 = __float2half_rn(v.y);
        __half h2 = __float2half_rn(v.z), h3 = __float2half_rn(v.w);
        *(__half2*)(j.hi[s] + i) = __halves2half2(h0, h1);
        *(__half2*)(j.hi[s] + i + 2) = __halves2half2(h2, h3);
        __half* lo = j.lo[s];
        if (lo) {
            *(__half2*)(lo + i) = __floats2half2_rn(v.x - __half2float(h0), v.y - __half2float(h1));
            *(__half2*)(lo + i + 2) = __floats2half2_rn(v.z - __half2float(h2), v.w - __half2float(h3));
        }
    }
}

// ---------------- shared 2-term GEMM mainloop, BK=64, 2-stage, 2 CTAs/SM ----------------
// Stage layout (halves): Ah[0,8192) Al[8192,16384) Bh[16384,24576)
#define GS_STAGE 24576
#define GS_BYTES (2 * GS_STAGE * 2)

__device__ __forceinline__ void gemm_mainloop(
    const __half* __restrict__ Ah, const __half* __restrict__ Al, int arow0,
    const __half* __restrict__ Bh, int N, int n0,
    __half* smp, float c[2][8][4], int tid)
{
    const int lane = tid & 31, warp = tid >> 5;
    const int m_off = (warp >> 1) * 32, n_off = (warp & 1) * 64;

    auto issue = [&](int stage, int k0) {
        __half* st = smp + stage * GS_STAGE;
#pragma unroll
        for (int i = 0; i < 4; i++) {
            int u = tid + i * 256;
            int aR = u >> 3, aC = u & 7;
            uint32_t d = cvta_s(st + aR * 64 + ((aC ^ (aR & 3)) << 3));
            size_t go = (size_t)(arow0 + aR) * D_MODEL + k0 + aC * 8;
            cp16(d, Ah + go);
            cp16(d + 16384, Al + go);
            int bR = u >> 4, bC = u & 15;
            cp16(cvta_s(st + 16384 + bR * 128 + ((bC ^ (bR & 7)) << 3)),
                 Bh + (size_t)(k0 + bR) * N + n0 + bC * 8);
        }
    };

    const int nkt = D_MODEL >> 6;   // 48
    issue(0, 0); cp_commit();

    for (int kt = 0; kt < nkt; kt++) {
        asm volatile("cp.async.wait_group 0;" ::: "memory");
        __syncthreads();
        if (kt + 1 < nkt) issue((kt + 1) & 1, (kt + 1) * 64);
        cp_commit();

        __half* st = smp + (kt & 1) * GS_STAGE;
        __half* Ash = st;
        __half* Asl = st + 8192;
        __half* Bsh = st + 16384;
#pragma unroll
        for (int kk = 0; kk < 4; kk++) {
            uint32_t ah[2][4], al[2][4];
#pragma unroll
            for (int mi = 0; mi < 2; mi++) {
                int row = m_off + mi * 16 + (lane & 15);
                int c8 = kk * 2 + (lane >> 4);
                int off = row * 64 + ((c8 ^ (row & 3)) << 3);
                ldsm4(ah[mi], cvta_s(Ash + off));
                ldsm4(al[mi], cvta_s(Asl + off));
            }
#pragma unroll
            for (int njp = 0; njp < 4; njp++) {
                int row = kk * 16 + (lane & 15);
                int c8 = (n_off >> 3) + njp * 2 + (lane >> 4);
                int off = row * 128 + ((c8 ^ (row & 7)) << 3);
                uint32_t bh[4];
                ldsm4t(bh, cvta_s(Bsh + off));
#pragma unroll
                for (int mi = 0; mi < 2; mi++) {
                    mma16816(c[mi][2 * njp], ah[mi], bh[0], bh[1]);
                    mma16816(c[mi][2 * njp], al[mi], bh[0], bh[1]);
                    mma16816(c[mi][2 * njp + 1], ah[mi], bh[2], bh[3]);
                    mma16816(c[mi][2 * njp + 1], al[mi], bh[2], bh[3]);
                }
            }
        }
        __syncthreads();
    }
}

// ---------------- fused QKV projection + RMSNorm + RoPE (one launch) ----------------
// grid (40, 36): y<4 -> text rows, else image rows; x<24 -> Q, x<32 -> K, else V.
__global__ __launch_bounds__(256, 2) void qkv_k(
    const float* __restrict__ bq, const float* __restrict__ bk, const float* __restrict__ bv,
    const float* __restrict__ abq, const float* __restrict__ abk, const float* __restrict__ abv,
    const float* __restrict__ nq, const float* __restrict__ nk,
    const float* __restrict__ anq, const float* __restrict__ ank,
    const float* __restrict__ rope, float qscale)
{
    extern __shared__ __align__(16) __half smp[];
    const int tid = threadIdx.x;
    const int lane = tid & 31, warp = tid >> 5;
    const int m_off = (warp >> 1) * 32, n_off = (warp & 1) * 64;
    const int by = blockIdx.y, bx = blockIdx.x;
    const bool txt = by < 4;
    const __half* Ah = txt ? g_ehsh : g_hsh;
    const __half* Al = txt ? g_ehsl : g_hsl;
    const int arow0 = txt ? by * 128 : (by - 4) * 128;
    const int jrow0 = by * 128;
    const int n0g = bx * 128;

    int seg, lc0, Nw;
    const __half* W;
    const float* bias;
    if (n0g < 3072)      { seg = 0; lc0 = n0g;        Nw = 3072; W = txt ? g_awq : g_wq; bias = txt ? abq : bq; }
    else if (n0g < 4096) { seg = 1; lc0 = n0g - 3072; Nw = 1024; W = txt ? g_awk : g_wk; bias = txt ? abk : bk; }
    else                 { seg = 2; lc0 = n0g - 4096; Nw = 1024; W = txt ? g_awv : g_wv; bias = txt ? abv : bv; }

    float c[2][8][4];
#pragma unroll
    for (int mi = 0; mi < 2; mi++)
#pragma unroll
        for (int nj = 0; nj < 8; nj++)
#pragma unroll
            for (int t = 0; t < 4; t++) c[mi][nj][t] = 0.f;

    gemm_mainloop(Ah, Al, arow0, W, Nw, lc0, smp, c, tid);

    const int head = lc0 >> 7;

    if (seg == 2) {
#pragma unroll
        for (int mi = 0; mi < 2; mi++) {
#pragma unroll
            for (int nj = 0; nj < 8; nj++) {
                int r0 = m_off + mi * 16 + (lane >> 2);
                int r1 = r0 + 8;
                int col = n_off + nj * 8 + ((lane & 3) << 1);
                float bx_ = bias[lc0 + col], by_ = bias[lc0 + col + 1];
                *(__half2*)(g_vb + ((size_t)head * S_TOT + jrow0 + r0) * HD + col) =
                    __floats2half2_rn(c[mi][nj][0] + bx_, c[mi][nj][1] + by_);
                *(__half2*)(g_vb + ((size_t)head * S_TOT + jrow0 + r1) * HD + col) =
                    __floats2half2_rn(c[mi][nj][2] + bx_, c[mi][nj][3] + by_);
            }
        }
        return;
    }

    // Q/K: add bias in place, then fused RMSNorm + RoPE with register/shuffle reduction.
#pragma unroll
    for (int mi = 0; mi < 2; mi++) {
#pragma unroll
        for (int nj = 0; nj < 8; nj++) {
            int col = n_off + nj * 8 + ((lane & 3) << 1);
            float bx_ = bias[lc0 + col], by_ = bias[lc0 + col + 1];
            c[mi][nj][0] += bx_; c[mi][nj][1] += by_;
            c[mi][nj][2] += bx_; c[mi][nj][3] += by_;
        }
    }
    float part[2][2];
#pragma unroll
    for (int mi = 0; mi < 2; mi++) {
        float s0 = 0.f, s1 = 0.f;
#pragma unroll
        for (int nj = 0; nj < 8; nj++) {
            s0 += c[mi][nj][0] * c[mi][nj][0] + c[mi][nj][1] * c[mi][nj][1];
            s1 += c[mi][nj][2] * c[mi][nj][2] + c[mi][nj][3] * c[mi][nj][3];
        }
        s0 += __shfl_xor_sync(0xffffffffu, s0, 1);
        s0 += __shfl_xor_sync(0xffffffffu, s0, 2);
        s1 += __shfl_xor_sync(0xffffffffu, s1, 1);
        s1 += __shfl_xor_sync(0xffffffffu, s1, 2);
        part[mi][0] = s0; part[mi][1] = s1;
    }
    float* red = (float*)smp;
    if ((lane & 3) == 0) {
#pragma unroll
        for (int mi = 0; mi < 2; mi++) {
            red[((warp * 2 + mi) * 2 + 0) * 8 + (lane >> 2)] = part[mi][0];
            red[((warp * 2 + mi) * 2 + 1) * 8 + (lane >> 2)] = part[mi][1];
        }
    }
    __syncthreads();

    const float* wnorm = (seg == 0) ? (txt ? anq : nq) : (txt ? ank : nk);
    const float oscale = (seg == 0) ? qscale : 1.0f;
    __half* outh = (seg == 0) ? g_qhb : g_kb;
    __half* outl = (seg == 0) ? g_qlb : (__half*)0;

#pragma unroll
    for (int mi = 0; mi < 2; mi++) {
#pragma unroll
        for (int rh = 0; rh < 2; rh++) {
            float sum = part[mi][rh] +
                red[(((warp ^ 1) * 2 + mi) * 2 + rh) * 8 + (lane >> 2)];
            float rr = rsqrtf(sum * (1.0f / HD) + 1e-6f);
            int r = m_off + mi * 16 + rh * 8 + (lane >> 2);
            int s = jrow0 + r;
            size_t rbase = ((size_t)head * S_TOT + s) * HD;
            const float* cosp = rope + (size_t)s * HD;
            const float* sinp = rope + (size_t)S_TOT * HD + (size_t)s * HD;
#pragma unroll
            for (int nj = 0; nj < 8; nj++) {
                int col = n_off + nj * 8 + ((lane & 3) << 1);
                float v0 = c[mi][nj][rh * 2 + 0];
                float v1 = c[mi][nj][rh * 2 + 1];
                float2 wn = *(const float2*)(wnorm + col);
                float y0 = v0 * rr * wn.x;
                float y1 = v1 * rr * wn.y;
                float2 cc = *(const float2*)(cosp + col);
                float2 sn = *(const float2*)(sinp + col);
                float o0 = (y0 * cc.x - y1 * sn.x) * oscale;
                float o1 = (y1 * cc.y + y0 * sn.y) * oscale;
                __half h0 = __float2half_rn(o0), h1 = __float2half_rn(o1);
                *(__half2*)(outh + rbase + col) = __halves2half2(h0, h1);
                if (outl) {
                    *(__half2*)(outl + rbase + col) =
                        __floats2half2_rn(o0 - __half2float(h0), o1 - __half2float(h1));
                }
            }
        }
    }
}

// ---------------- fused output projections (one launch) ----------------
__global__ __launch_bounds__(256, 2) void oproj_k(
    const float* __restrict__ bout, const float* __restrict__ baout, float* __restrict__ out)
{
    extern __shared__ __align__(16) __half smp[];
    const int tid = threadIdx.x;
    const int lane = tid & 31, warp = tid >> 5;
    const int m_off = (warp >> 1) * 32, n_off = (warp & 1) * 64;
    const int by = blockIdx.y, bx = blockIdx.x;
    const bool txt = by < 4;
    const int arow0 = by * 128;
    const int crow0 = txt ? 4096 + by * 128 : by * 128 - 512;
    const __half* W = txt ? g_waout : g_wout;
    const float* bias = txt ? baout : bout;
    const int n0 = bx * 128;

    float c[2][8][4];
#pragma unroll
    for (int mi = 0; mi < 2; mi++)
#pragma unroll
        for (int nj = 0; nj < 8; nj++)
#pragma unroll
            for (int t = 0; t < 4; t++) c[mi][nj][t] = 0.f;

    gemm_mainloop(g_oh, g_ol, arow0, W, 3072, n0, smp, c, tid);

#pragma unroll
    for (int mi = 0; mi < 2; mi++) {
#pragma unroll
        for (int nj = 0; nj < 8; nj++) {
            int r0 = m_off + mi * 16 + (lane >> 2);
            int r1 = r0 + 8;
            int col = n0 + n_off + nj * 8 + ((lane & 3) << 1);
            float bx_ = bias[col], by_ = bias[col + 1];
            *(float2*)(out + (size_t)(crow0 + r0) * 3072 + col) =
                make_float2(c[mi][nj][0] + bx_, c[mi][nj][1] + by_);
            *(float2*)(out + (size_t)(crow0 + r1) * 3072 + col) =
                make_float2(c[mi][nj][2] + bx_, c[mi][nj][3] + by_);
        }
    }
}

// ---------------- flash attention: split-q QK^T, 256 thr, 128-row tile (R13 best config) ----------------
#define AT_STEPS (S_TOT / 64)
#define AT_SMEM ((16384 + 16384 + 2 * 8192 + 2 * 8192) * 2)

__global__ __launch_bounds__(256) void attn_k(
    const __half* __restrict__ qh, const __half* __restrict__ qlg,
    const __half* __restrict__ kg, const __half* __restrict__ vg,
    __half* __restrict__ oh, __half* __restrict__ ol)
{
    extern __shared__ __align__(16) __half sm[];
    __half* Qh = sm;
    __half* Ql = sm + 16384;
    __half* Kb = sm + 32768;
    __half* Vb = sm + 49152;
    const int tid = threadIdx.x, lane = tid & 31, w = tid >> 5;
    const int h = blockIdx.y, m0 = blockIdx.x * 128;
    const int kvh = h / 3;

    const __half* qbh = qh + ((size_t)h * S_TOT + m0) * HD;
    const __half* qbl = qlg + ((size_t)h * S_TOT + m0) * HD;
#pragma unroll
    for (int t = 0; t < 8; t++) {
        int cid = tid + t * 256;
        int r = cid >> 4, c8 = cid & 15;
        int off = r * 128 + ((c8 ^ (r & 7)) << 3);
        cp16(cvta_s(Qh + off), qbh + (size_t)r * HD + c8 * 8);
        cp16(cvta_s(Ql + off), qbl + (size_t)r * HD + c8 * 8);
    }

    const __half* kb0 = kg + (size_t)kvh * S_TOT * HD;
    const __half* vb0 = vg + (size_t)kvh * S_TOT * HD;
    auto issue_kv = [&](int n, int buf) {
        const __half* kb = kb0 + (size_t)n * 64 * HD;
        const __half* vb = vb0 + (size_t)n * 64 * HD;
        __half* Kd = Kb + buf * 8192;
        __half* Vd = Vb + buf * 8192;
#pragma unroll
        for (int t = 0; t < 4; t++) {
            int cid = tid + t * 256;
            int r = cid >> 4, c8 = cid & 15;
            int off = r * 128 + ((c8 ^ (r & 7)) << 3);
            cp16(cvta_s(Kd + off), kb + (size_t)r * HD + c8 * 8);
            cp16(cvta_s(Vd + off), vb + (size_t)r * HD + c8 * 8);
        }
    };
    issue_kv(0, 0);
    cp_commit();

    float oa[16][4];
#pragma unroll
    for (int nj = 0; nj < 16; nj++)
#pragma unroll
        for (int t = 0; t < 4; t++) oa[nj][t] = 0.f;
    float mI0 = -INFINITY, mI1 = -INFINITY, lI0 = 0.f, lI1 = 0.f;

    for (int it = 0; it < AT_STEPS; it++) {
        asm volatile("cp.async.wait_group 0;" ::: "memory");
        __syncthreads();
        if (it + 1 < AT_STEPS) issue_kv(it + 1, (it + 1) & 1);
        cp_commit();
        __half* Ks = Kb + (it & 1) * 8192;
        __half* Vs = Vb + (it & 1) * 8192;

        float s[8][4];
#pragma unroll
        for (int j = 0; j < 8; j++)
#pragma unroll
            for (int t = 0; t < 4; t++) s[j][t] = 0.f;

#pragma unroll
        for (int dk = 0; dk < 8; dk++) {
            uint32_t a[4], al[4];
            {
                int row = w * 16 + (lane & 15);
                int c8 = dk * 2 + (lane >> 4);
                int off = row * 128 + ((c8 ^ (row & 7)) << 3);
                ldsm4(a, cvta_s(Qh + off));
                ldsm4(al, cvta_s(Ql + off));
            }
#pragma unroll
            for (int njp = 0; njp < 4; njp++) {
                int row = njp * 16 + (lane & 7) + ((lane >> 4) << 3);
                int c8 = dk * 2 + ((lane >> 3) & 1);
                uint32_t b[4];
                ldsm4(b, cvta_s(Ks + row * 128 + ((c8 ^ (row & 7)) << 3)));
                mma16816(s[2 * njp], a, b[0], b[1]);
                mma16816(s[2 * njp], al, b[0], b[1]);
                mma16816(s[2 * njp + 1], a, b[2], b[3]);
                mma16816(s[2 * njp + 1], al, b[2], b[3]);
            }
        }

        float mx0 = -INFINITY, mx1 = -INFINITY;
#pragma unroll
        for (int j = 0; j < 8; j++) {
            mx0 = fmaxf(mx0, fmaxf(s[j][0], s[j][1]));
            mx1 = fmaxf(mx1, fmaxf(s[j][2], s[j][3]));
        }
        mx0 = fmaxf(mx0, __shfl_xor_sync(0xffffffffu, mx0, 1));
        mx0 = fmaxf(mx0, __shfl_xor_sync(0xffffffffu, mx0, 2));
        mx1 = fmaxf(mx1, __shfl_xor_sync(0xffffffffu, mx1, 1));
        mx1 = fmaxf(mx1, __shfl_xor_sync(0xffffffffu, mx1, 2));
        float mn0 = fmaxf(mI0, mx0), mn1 = fmaxf(mI1, mx1);
        float al0 = exp2f(mI0 - mn0), al1 = exp2f(mI1 - mn1);
        mI0 = mn0; mI1 = mn1;
        float rs0 = 0.f, rs1 = 0.f;
#pragma unroll
        for (int j = 0; j < 8; j++) {
            s[j][0] = exp2f(s[j][0] - mn0);
            s[j][1] = exp2f(s[j][1] - mn0);
            s[j][2] = exp2f(s[j][2] - mn1);
            s[j][3] = exp2f(s[j][3] - mn1);
            rs0 += s[j][0] + s[j][1];
            rs1 += s[j][2] + s[j][3];
        }
        rs0 += __shfl_xor_sync(0xffffffffu, rs0, 1);
        rs0 += __shfl_xor_sync(0xffffffffu, rs0, 2);
        rs1 += __shfl_xor_sync(0xffffffffu, rs1, 1);
        rs1 += __shfl_xor_sync(0xffffffffu, rs1, 2);
        lI0 = lI0 * al0 + rs0;
        lI1 = lI1 * al1 + rs1;
#pragma unroll
        for (int nj = 0; nj < 16; nj++) {
            oa[nj][0] *= al0; oa[nj][1] *= al0;
            oa[nj][2] *= al1; oa[nj][3] *= al1;
        }
        uint32_t pa[4][4];
#pragma unroll
        for (int kc = 0; kc < 4; kc++) {
            pa[kc][0] = packh2(s[2 * kc][0], s[2 * kc][1]);
            pa[kc][1] = packh2(s[2 * kc][2], s[2 * kc][3]);
            pa[kc][2] = packh2(s[2 * kc + 1][0], s[2 * kc + 1][1]);
            pa[kc][3] = packh2(s[2 * kc + 1][2], s[2 * kc + 1][3]);
        }
#pragma unroll
        for (int kc = 0; kc < 4; kc++) {
#pragma unroll
            for (int njp = 0; njp < 8; njp++) {
                int row = kc * 16 + (lane & 15);
                int c8 = njp * 2 + (lane >> 4);
                uint32_t b[4];
                ldsm4t(b, cvta_s(Vs + row * 128 + ((c8 ^ (row & 7)) << 3)));
                mma16816(oa[2 * njp], pa[kc], b[0], b[1]);
                mma16816(oa[2 * njp + 1], pa[kc], b[2], b[3]);
            }
        }
    }

    float inv0 = 1.f / lI0, inv1 = 1.f / lI1;
    int gr0 = m0 + w * 16 + (lane >> 2);
    int gr1 = gr0 + 8;
#pragma unroll
    for (int nj = 0; nj < 16; nj++) {
        int col = h * 128 + nj * 8 + ((lane & 3) << 1);
        float v00 = oa[nj][0] * inv0, v01 = oa[nj][1] * inv0;
        float v10 = oa[nj][2] * inv1, v11 = oa[nj][3] * inv1;
        __half h00 = __float2half_rn(v00), h01 = __float2half_rn(v01);
        __half h10 = __float2half_rn(v10), h11 = __float2half_rn(v11);
        *(__half2*)(oh + (size_t)gr0 * 3072 + col) = __halves2half2(h00, h01);
        *(__half2*)(oh + (size_t)gr1 * 3072 + col) = __halves2half2(h10, h11);
        *(__half2*)(ol + (size_t)gr0 * 3072 + col) =
            __floats2half2_rn(v00 - __half2float(h00), v01 - __half2float(h01));
        *(__half2*)(ol + (size_t)gr1 * 3072 + col) =
            __floats2half2_rn(v10 - __half2float(h10), v11 - __half2float(h11));
    }
}

// ---------------- launch ----------------
extern "C" void kernel_launch(void* const* d_in, const int* in_sizes, int n_in,
                              void* d_out, int out_size)
{
    const float* hs    = (const float*)d_in[0];
    const float* ehs   = (const float*)d_in[1];
    const float* rope  = (const float*)d_in[2];
    const float* Wq    = (const float*)d_in[3];
    const float* bq    = (const float*)d_in[4];
    const float* Wk    = (const float*)d_in[5];
    const float* bk    = (const float*)d_in[6];
    const float* Wv    = (const float*)d_in[7];
    const float* bv    = (const float*)d_in[8];
    const float* aWq   = (const float*)d_in[9];
    const float* abq   = (const float*)d_in[10];
    const float* aWk   = (const float*)d_in[11];
    const float* abk   = (const float*)d_in[12];
    const float* aWv   = (const float*)d_in[13];
    const float* abv   = (const float*)d_in[14];
    const float* nq    = (const float*)d_in[15];
    const float* nk    = (const float*)d_in[16];
    const float* anq   = (const float*)d_in[17];
    const float* ank   = (const float*)d_in[18];
    const float* Wout  = (const float*)d_in[19];
    const float* bout  = (const float*)d_in[20];
    const float* Waout = (const float*)d_in[21];
    const float* baout = (const float*)d_in[22];
    float* out = (float*)d_out;

    __half *hsh, *hsl, *ehsh, *ehsl;
    __half *wq, *wk, *wv, *awq, *awk, *awv, *wout, *waout;
    __half *qhb, *qlb, *k, *v, *oh, *ol;
    cudaGetSymbolAddress((void**)&hsh, g_hsh);
    cudaGetSymbolAddress((void**)&hsl, g_hsl);
    cudaGetSymbolAddress((void**)&ehsh, g_ehsh);
    cudaGetSymbolAddress((void**)&ehsl, g_ehsl);
    cudaGetSymbolAddress((void**)&wq, g_wq);
    cudaGetSymbolAddress((void**)&wk, g_wk);
    cudaGetSymbolAddress((void**)&wv, g_wv);
    cudaGetSymbolAddress((void**)&awq, g_awq);
    cudaGetSymbolAddress((void**)&awk, g_awk);
    cudaGetSymbolAddress((void**)&awv, g_awv);
    cudaGetSymbolAddress((void**)&wout, g_wout);
    cudaGetSymbolAddress((void**)&waout, g_waout);
    cudaGetSymbolAddress((void**)&qhb, g_qhb);
    cudaGetSymbolAddress((void**)&qlb, g_qlb);
    cudaGetSymbolAddress((void**)&k, g_kb);
    cudaGetSymbolAddress((void**)&v, g_vb);
    cudaGetSymbolAddress((void**)&oh, g_oh);
    cudaGetSymbolAddress((void**)&ol, g_ol);

    // all fp32 -> fp16 conversions: one launch (10 jobs; first 2 emit hi+lo)
    {
        CvtJobs j;
        const float* srcs[10] = {hs, ehs, Wq, Wk, Wv, aWq, aWk, aWv, Wout, Waout};
        __half* his[10] = {hsh, ehsh, wq, wk, wv, awq, awk, awv, wout, waout};
        __half* los[10] = {hsl, ehsl, 0, 0, 0, 0, 0, 0, 0, 0};
        int sizes[10] = {S_IMG * D_MODEL, S_TXT * D_MODEL,
                         D_MODEL * 3072, D_MODEL * 1024, D_MODEL * 1024,
                         D_MODEL * 3072, D_MODEL * 1024, D_MODEL * 1024,
                         3072 * D_MODEL, 3072 * D_MODEL};
        int acc = 0;
        for (int i = 0; i < 10; i++) {
            j.src[i] = srcs[i];
            j.hi[i] = his[i];
            j.lo[i] = los[i];
            j.cum[i] = acc;
            acc += sizes[i] / 4;
        }
        j.cum[10] = acc;
        cvt_all<<<1184, 256>>>(j, acc);
    }

    cudaFuncSetAttribute(qkv_k, cudaFuncAttributeMaxDynamicSharedMemorySize, GS_BYTES);
    cudaFuncSetAttribute(oproj_k, cudaFuncAttributeMaxDynamicSharedMemorySize, GS_BYTES);

    // fused QKV projections + RMSNorm + RoPE: one launch
    const float qscale = 0.08838834764831845f * 1.4426950408889634f;
    qkv_k<<<dim3(40, 36), 256, GS_BYTES>>>(bq, bk, bv, abq, abk, abv,
                                           nq, nk, anq, ank, rope, qscale);

    // attention
    cudaFuncSetAttribute(attn_k, cudaFuncAttributeMaxDynamicSharedMemorySize, AT_SMEM);
    attn_k<<<dim3(S_TOT / 128, NH), 256, AT_SMEM>>>(qhb, qlb, k, v, oh, ol);

    // fused output projections: one launch for hid + enc
    oproj_k<<<dim3(24, 36), 256, GS_BYTES>>>(bout, baout, out);
}